// round 1
// baseline (speedup 1.0000x reference)
#include <cuda_runtime.h>
#include <math.h>

#define BIG_NEG -1000000000.0f
#define D     64
#define C1    32
#define CAUG  33
#define N1    512
#define NAUG  513
#define KK    32
#define BATCH 4

// Scratch (allocations forbidden -> device globals)
__device__ float g_Minv[D * D];
__device__ float g_logdet;
__device__ float g_trans_aug[CAUG * CAUG];
__device__ float g_init_aug[CAUG];
__device__ float g_len_aug[KK * CAUG];
__device__ float g_vc[C1 * D];
__device__ float g_qc[C1];
__device__ float g_em_aug[BATCH * NAUG * CAUG];

// ---------------------------------------------------------------------------
// Kernel A: Gauss-Jordan inverse + logdet of cov (PD, no pivoting needed),
// log-softmaxes, augmented tables, v_c = Minv m_c, q_c = m_c . v_c
// ---------------------------------------------------------------------------
__global__ __launch_bounds__(1024) void prep_kernel(
    const float* __restrict__ cov, const float* __restrict__ means,
    const float* __restrict__ plr, const float* __restrict__ tl,
    const float* __restrict__ il) {
  __shared__ float M[D][2 * D + 1];  // [A | I], padded row (129 ≡ 1 mod 32)
  int tid = threadIdx.x;

  for (int e = tid; e < D * D; e += 1024) {
    int r = e >> 6, c = e & 63;
    M[r][c] = cov[e];
    M[r][D + c] = (r == c) ? 1.0f : 0.0f;
  }
  __syncthreads();

  float lacc = 0.0f;
  int i = tid >> 4;            // row 0..63
  int j0 = (tid & 15) * 8;     // 8-col chunk of 128
  for (int k = 0; k < D; k++) {
    float piv = M[k][k];
    float pinv = 1.0f / piv;
    float lik = M[i][k] * pinv;
    float pr[8];
#pragma unroll
    for (int jj = 0; jj < 8; jj++) pr[jj] = M[k][j0 + jj];
    if (tid == 0) lacc += logf(piv);
    __syncthreads();
    if (i == k) {
#pragma unroll
      for (int jj = 0; jj < 8; jj++) M[k][j0 + jj] = pr[jj] * pinv;
    } else {
#pragma unroll
      for (int jj = 0; jj < 8; jj++) M[i][j0 + jj] -= lik * pr[jj];
    }
    __syncthreads();
  }
  if (tid == 0) g_logdet = lacc;

  // Minv -> global
  for (int e = tid; e < D * D; e += 1024)
    g_Minv[e] = M[e >> 6][D + (e & 63)];

  // v_c[c][d] = sum_e Minv[d][e] * means[c][e]
  for (int e = tid; e < C1 * D; e += 1024) {
    int c = e >> 6, dd = e & 63;
    float s = 0.0f;
#pragma unroll 8
    for (int ee = 0; ee < D; ee++) s += M[dd][D + ee] * means[c * D + ee];
    g_vc[e] = s;
  }
  __syncthreads();  // g_vc visible within block after sync

  if (tid < C1) {
    float s = 0.0f;
#pragma unroll 8
    for (int ee = 0; ee < D; ee++) s += means[tid * D + ee] * g_vc[tid * D + ee];
    g_qc[tid] = s;
  }

  // trans = log_softmax over axis 0 (per column), diag masked.
  // warp w handles column j=w, lane = i.
  {
    int w = tid >> 5, lane = tid & 31;
    float x = (lane == w) ? BIG_NEG : tl[lane * C1 + w];
    float m = x;
#pragma unroll
    for (int o = 16; o; o >>= 1) m = fmaxf(m, __shfl_xor_sync(0xffffffffu, m, o));
    float s = expf(x - m);
#pragma unroll
    for (int o = 16; o; o >>= 1) s += __shfl_xor_sync(0xffffffffu, s, o);
    g_trans_aug[lane * CAUG + w] = (x - m) - logf(s);
  }

  // init log_softmax (warp 0)
  if (tid < 32) {
    float x = il[tid];
    float m = x;
#pragma unroll
    for (int o = 16; o; o >>= 1) m = fmaxf(m, __shfl_xor_sync(0xffffffffu, m, o));
    float s = expf(x - m);
#pragma unroll
    for (int o = 16; o; o >>= 1) s += __shfl_xor_sync(0xffffffffu, s, o);
    g_init_aug[tid] = (x - m) - logf(s);
    if (tid == 0) g_init_aug[C1] = BIG_NEG;
  }

  // trans_aug row C1 = 0.0 (all 33 cols, including [32][32]); col C1 = BIG_NEG for i<C1
  if (tid < CAUG) g_trans_aug[C1 * CAUG + tid] = 0.0f;
  if (tid >= 64 && tid < 64 + C1) g_trans_aug[(tid - 64) * CAUG + C1] = BIG_NEG;

  // len_aug[k][j]
  for (int e = tid; e < KK * CAUG; e += 1024) {
    int k = e / CAUG, j = e - k * CAUG;
    float v;
    if (j < C1)
      v = (float)k * plr[j] - expf(plr[j]) - lgammaf((float)(k + 1));
    else
      v = (k == 1) ? 0.0f : BIG_NEG;
    g_len_aug[e] = v;
  }
}

// ---------------------------------------------------------------------------
// Kernel B: em_aug[b][n][c]; one block per (n, b), 64 threads
// ---------------------------------------------------------------------------
__global__ __launch_bounds__(64) void em_kernel(
    const float* __restrict__ features, const int* __restrict__ lengths) {
  int n = blockIdx.x;   // 0..512
  int bb = blockIdx.y;  // 0..3
  int tid = threadIdx.x;
  float* row = &g_em_aug[(bb * NAUG + n) * CAUG];

  bool isLen = false;
#pragma unroll
  for (int q = 0; q < BATCH; q++) isLen |= (lengths[q] == n);
  float eos = isLen ? 0.0f : BIG_NEG;  // shared across batch (matches reference)

  int len = lengths[bb];
  if (n >= len) {  // covers n == N1 too (len <= 512)
    if (tid < C1) row[tid] = BIG_NEG;
    if (tid == C1) row[C1] = eos;
    return;
  }

  __shared__ float f[D];
  __shared__ float red[D];
  f[tid] = features[((size_t)(bb * N1 + n)) * D + tid];
  __syncthreads();

  float s = 0.0f;
  const float* Mrow = &g_Minv[tid * D];
#pragma unroll 8
  for (int e = 0; e < D; e++) s += Mrow[e] * f[e];
  red[tid] = s * f[tid];
  __syncthreads();

  if (tid == C1) row[C1] = eos;
  if (tid < 32) {
    float v = red[tid] + red[tid + 32];
#pragma unroll
    for (int o = 16; o; o >>= 1) v += __shfl_xor_sync(0xffffffffu, v, o);
    float dot = 0.0f;
    const float* vc = &g_vc[tid * D];
#pragma unroll 8
    for (int e = 0; e < D; e++) dot += vc[e] * f[e];
    // d*log(2*pi) = 117.6241322501981
    float em = -0.5f * (v + g_qc[tid] - 2.0f * dot + 117.6241322501981f + g_logdet);
    row[tid] = em;
  }
}

// ---------------------------------------------------------------------------
// Kernel C: the 285 MB store kernel. One block per (t, b).
// out[k,i,j] = T[i,j] + A[k,j]  (+ em_last[b,i] on the single k = 512 - t)
// ---------------------------------------------------------------------------
__global__ __launch_bounds__(256) void score_kernel(float* __restrict__ out) {
  int t = blockIdx.x;   // 0..511
  int bb = blockIdx.y;  // 0..3
  int tid = threadIdx.x;

  __shared__ float T[CAUG * CAUG];          // 1089
  __shared__ float Arr[KK * CAUG];          // 1056: len_aug + wins (+ init at t=0)
  __shared__ float E[CAUG];                 // em_last[b][:]
  __shared__ float Wrow[(KK - 1) * CAUG];   // em_aug rows t .. t+30 (0 past end)

  for (int e = tid; e < CAUG * CAUG; e += 256) T[e] = g_trans_aug[e];
  if (tid < CAUG) E[tid] = g_em_aug[(bb * NAUG + N1) * CAUG + tid];
  for (int e = tid; e < (KK - 1) * CAUG; e += 256) {
    int r = e / CAUG, j = e - r * CAUG;
    int n = t + r;
    Wrow[e] = (n <= N1) ? g_em_aug[(bb * NAUG + n) * CAUG + j] : 0.0f;
  }
  __syncthreads();

  // windowed running sums: wins[k] = sum of em rows t..t+k-1 (clipped)
  if (tid < CAUG) {
    int j = tid;
    float ia = (t == 0) ? g_init_aug[j] : 0.0f;
    float w = 0.0f;
    Arr[j] = g_len_aug[j] + ia;  // k = 0: empty window
#pragma unroll
    for (int k = 1; k < KK; k++) {
      w += Wrow[(k - 1) * CAUG + j];
      Arr[k * CAUG + j] = w + g_len_aug[k * CAUG + j] + ia;
    }
  }
  __syncthreads();

  float* obase = out + (size_t)(bb * N1 + t) * (KK * CAUG * CAUG);

  for (int pos = tid; pos < CAUG * CAUG; pos += 256) {
    float tv = T[pos];
    int j = pos % CAUG;
    float* op = obase + pos;
#pragma unroll
    for (int k = 0; k < KK; k++)
      op[k * CAUG * CAUG] = tv + Arr[k * CAUG + j];  // coalesced STG.32
  }

  // rare per-i correction: t + k == 512, k in [1,31]  (t in [481,511])
  int kspec = N1 - t;
  if (kspec >= 1 && kspec < KK) {
    for (int pos = tid; pos < CAUG * CAUG; pos += 256) {
      int i2 = pos / CAUG;
      int j = pos - i2 * CAUG;
      // same thread rewrote same address in the loop above -> ordered, OK
      obase[kspec * CAUG * CAUG + pos] = T[pos] + Arr[kspec * CAUG + j] + E[i2];
    }
  }
}

// ---------------------------------------------------------------------------
extern "C" void kernel_launch(void* const* d_in, const int* in_sizes, int n_in,
                              void* d_out, int out_size) {
  const float* features = (const float*)d_in[0];
  const int*   lengths  = (const int*)d_in[1];
  const float* means    = (const float*)d_in[2];
  const float* cov      = (const float*)d_in[3];
  const float* plr      = (const float*)d_in[4];
  const float* tl       = (const float*)d_in[5];
  const float* il       = (const float*)d_in[6];
  float* out = (float*)d_out;

  prep_kernel<<<1, 1024>>>(cov, means, plr, tl, il);
  em_kernel<<<dim3(NAUG, BATCH), 64>>>(features, lengths);
  score_kernel<<<dim3(N1, BATCH), 256>>>(out);
}

// round 4
// speedup vs baseline: 1.0303x; 1.0303x over previous
#include <cuda_runtime.h>
#include <math.h>

#define BIG_NEG -1000000000.0f
#define D     64
#define C1    32
#define CAUG  33
#define N1    512
#define NAUG  513
#define KK    32
#define BATCH 4
#define GJS   65   // 64 cols + 1 pad

// Scratch (allocations forbidden -> device globals)
__device__ float g_Minv[D * D];
__device__ float g_logdet;
__device__ float g_trans_aug[CAUG * CAUG];
__device__ float g_init_aug[CAUG];
__device__ float g_len_aug[KK * CAUG];
__device__ float g_vc[C1 * D];
__device__ float g_qc[C1];
__device__ float g_em_aug[BATCH * NAUG * CAUG];

// ---------------------------------------------------------------------------
// Kernel A: in-place Gauss-Jordan "exchange step" inverse + logdet,
// double-buffered (1 barrier / iter), static smem (33.3 KB), branch-free
// reciprocal. Then log-softmaxes, augmented tables, v_c, q_c.
//
// Exchange step at pivot k (no pivoting needed; cov is PD):
//   p = 1/a_kk
//   b_kk = p;  b_kj = a_kj*p (j!=k);  b_ik = -a_ik*p (i!=k)
//   b_ij = a_ij - a_ik*p*a_kj
// After k = 0..D-1, buffer holds A^{-1}.
// ---------------------------------------------------------------------------
__global__ __launch_bounds__(1024) void prep_kernel(
    const float* __restrict__ cov, const float* __restrict__ means,
    const float* __restrict__ plr, const float* __restrict__ tl,
    const float* __restrict__ il) {
  __shared__ float bufA[D * GJS];
  __shared__ float bufB[D * GJS];
  int tid = threadIdx.x;
  int i = tid >> 4;            // row 0..63
  int j0 = (tid & 15) * 4;     // 4-col chunk of 64

  for (int e = tid; e < D * D; e += 1024)
    bufA[(e >> 6) * GJS + (e & 63)] = cov[e];
  __syncthreads();

  float lacc = 0.0f;
  float* cur = bufA;
  float* nxt = bufB;
#pragma unroll 1
  for (int k = 0; k < D; k++) {
    float piv = cur[k * GJS + k];
    float p = __fdividef(1.0f, piv);           // MUFU path, no slow-path branch
    float aik = cur[i * GJS + k];
    if (tid == 0) lacc += __logf(piv);
#pragma unroll
    for (int jj = 0; jj < 4; jj++) {
      int j = j0 + jj;
      float akj = cur[k * GJS + j];
      float v = fmaf(-aik * p, akj, cur[i * GJS + j]);
      if (j == k) v = -aik * p;
      if (i == k) v = akj * p;
      if (i == k && j == k) v = p;
      nxt[i * GJS + j] = v;
    }
    __syncthreads();
    float* t2 = cur; cur = nxt; nxt = t2;
  }
  // D=64 iterations (even) -> result in bufA == cur
  if (tid == 0) g_logdet = lacc;

  // Minv -> global
  for (int e = tid; e < D * D; e += 1024)
    g_Minv[e] = cur[(e >> 6) * GJS + (e & 63)];

  // v_c[c][d] = sum_e Minv[d][e] * means[c][e]
  for (int e = tid; e < C1 * D; e += 1024) {
    int c = e >> 6, dd = e & 63;
    float s = 0.0f;
#pragma unroll 8
    for (int ee = 0; ee < D; ee++)
      s += cur[dd * GJS + ee] * means[c * D + ee];
    g_vc[e] = s;
  }
  __syncthreads();

  if (tid < C1) {
    float s = 0.0f;
#pragma unroll 8
    for (int ee = 0; ee < D; ee++) s += means[tid * D + ee] * g_vc[tid * D + ee];
    g_qc[tid] = s;
  }

  // trans = log_softmax over axis 0 (per column), diag masked. warp w = col j.
  {
    int w = tid >> 5, lane = tid & 31;
    float x = (lane == w) ? BIG_NEG : tl[lane * C1 + w];
    float m = x;
#pragma unroll
    for (int o = 16; o; o >>= 1) m = fmaxf(m, __shfl_xor_sync(0xffffffffu, m, o));
    float s = expf(x - m);
#pragma unroll
    for (int o = 16; o; o >>= 1) s += __shfl_xor_sync(0xffffffffu, s, o);
    g_trans_aug[lane * CAUG + w] = (x - m) - logf(s);
  }

  // init log_softmax (warp 0)
  if (tid < 32) {
    float x = il[tid];
    float m = x;
#pragma unroll
    for (int o = 16; o; o >>= 1) m = fmaxf(m, __shfl_xor_sync(0xffffffffu, m, o));
    float s = expf(x - m);
#pragma unroll
    for (int o = 16; o; o >>= 1) s += __shfl_xor_sync(0xffffffffu, s, o);
    g_init_aug[tid] = (x - m) - logf(s);
    if (tid == 0) g_init_aug[C1] = BIG_NEG;
  }

  // trans_aug row C1 = 0.0; col C1 = BIG_NEG for i<C1
  if (tid < CAUG) g_trans_aug[C1 * CAUG + tid] = 0.0f;
  if (tid >= 64 && tid < 64 + C1) g_trans_aug[(tid - 64) * CAUG + C1] = BIG_NEG;

  // len_aug[k][j]
  for (int e = tid; e < KK * CAUG; e += 1024) {
    int k = e / CAUG, j = e - k * CAUG;
    float v;
    if (j < C1)
      v = (float)k * plr[j] - expf(plr[j]) - lgammaf((float)(k + 1));
    else
      v = (k == 1) ? 0.0f : BIG_NEG;
    g_len_aug[e] = v;
  }
}

// ---------------------------------------------------------------------------
// Kernel B: em_aug[b][n][c]; one block per (n, b), 64 threads
// ---------------------------------------------------------------------------
__global__ __launch_bounds__(64) void em_kernel(
    const float* __restrict__ features, const int* __restrict__ lengths) {
  int n = blockIdx.x;   // 0..512
  int bb = blockIdx.y;  // 0..3
  int tid = threadIdx.x;
  float* row = &g_em_aug[(bb * NAUG + n) * CAUG];

  bool isLen = false;
#pragma unroll
  for (int q = 0; q < BATCH; q++) isLen |= (lengths[q] == n);
  float eos = isLen ? 0.0f : BIG_NEG;  // shared across batch (matches reference)

  int len = lengths[bb];
  if (n >= len) {  // covers n == N1 too (len <= 512)
    if (tid < C1) row[tid] = BIG_NEG;
    if (tid == C1) row[C1] = eos;
    return;
  }

  __shared__ float f[D];
  __shared__ float red[D];
  f[tid] = features[((size_t)(bb * N1 + n)) * D + tid];
  __syncthreads();

  float s = 0.0f;
  const float* Mrow = &g_Minv[tid * D];
#pragma unroll 8
  for (int e = 0; e < D; e++) s += Mrow[e] * f[e];
  red[tid] = s * f[tid];
  __syncthreads();

  if (tid == C1) row[C1] = eos;
  if (tid < 32) {
    float v = red[tid] + red[tid + 32];
#pragma unroll
    for (int o = 16; o; o >>= 1) v += __shfl_xor_sync(0xffffffffu, v, o);
    float dot = 0.0f;
    const float* vc = &g_vc[tid * D];
#pragma unroll 8
    for (int e = 0; e < D; e++) dot += vc[e] * f[e];
    // d*log(2*pi) = 117.6241322501981
    float em = -0.5f * (v + g_qc[tid] - 2.0f * dot + 117.6241322501981f + g_logdet);
    row[tid] = em;
  }
}

// ---------------------------------------------------------------------------
// Kernel C: the 285 MB store kernel. One block per (t, b).
// out[k,i,j] = T[i,j] + A[k,j]  (+ em_last[b,i] on the single k = 512 - t)
// ---------------------------------------------------------------------------
__global__ __launch_bounds__(256) void score_kernel(float* __restrict__ out) {
  int t = blockIdx.x;   // 0..511
  int bb = blockIdx.y;  // 0..3
  int tid = threadIdx.x;

  __shared__ float T[CAUG * CAUG];          // 1089
  __shared__ float Arr[KK * CAUG];          // 1056: len_aug + wins (+ init at t=0)
  __shared__ float E[CAUG];                 // em_last[b][:]
  __shared__ float Wrow[(KK - 1) * CAUG];   // em_aug rows t .. t+30 (0 past end)

  for (int e = tid; e < CAUG * CAUG; e += 256) T[e] = g_trans_aug[e];
  if (tid < CAUG) E[tid] = g_em_aug[(bb * NAUG + N1) * CAUG + tid];
  for (int e = tid; e < (KK - 1) * CAUG; e += 256) {
    int r = e / CAUG, j = e - r * CAUG;
    int n = t + r;
    Wrow[e] = (n <= N1) ? g_em_aug[(bb * NAUG + n) * CAUG + j] : 0.0f;
  }
  __syncthreads();

  // windowed running sums: wins[k] = sum of em rows t..t+k-1 (clipped)
  if (tid < CAUG) {
    int j = tid;
    float ia = (t == 0) ? g_init_aug[j] : 0.0f;
    float w = 0.0f;
    Arr[j] = g_len_aug[j] + ia;  // k = 0: empty window
#pragma unroll
    for (int k = 1; k < KK; k++) {
      w += Wrow[(k - 1) * CAUG + j];
      Arr[k * CAUG + j] = w + g_len_aug[k * CAUG + j] + ia;
    }
  }
  __syncthreads();

  float* obase = out + (size_t)(bb * N1 + t) * (KK * CAUG * CAUG);

  for (int pos = tid; pos < CAUG * CAUG; pos += 256) {
    float tv = T[pos];
    int j = pos % CAUG;
    float* op = obase + pos;
#pragma unroll
    for (int k = 0; k < KK; k++)
      __stcs(op + k * CAUG * CAUG, tv + Arr[k * CAUG + j]);  // streaming stores
  }

  // rare per-i correction: t + k == 512, k in [1,31]  (t in [481,511])
  int kspec = N1 - t;
  if (kspec >= 1 && kspec < KK) {
    for (int pos = tid; pos < CAUG * CAUG; pos += 256) {
      int i2 = pos / CAUG;
      int j = pos - i2 * CAUG;
      // same thread rewrote same address in the loop above -> ordered, OK
      __stcs(obase + kspec * CAUG * CAUG + pos,
             T[pos] + Arr[kspec * CAUG + j] + E[i2]);
    }
  }
}

// ---------------------------------------------------------------------------
extern "C" void kernel_launch(void* const* d_in, const int* in_sizes, int n_in,
                              void* d_out, int out_size) {
  const float* features = (const float*)d_in[0];
  const int*   lengths  = (const int*)d_in[1];
  const float* means    = (const float*)d_in[2];
  const float* cov      = (const float*)d_in[3];
  const float* plr      = (const float*)d_in[4];
  const float* tl       = (const float*)d_in[5];
  const float* il       = (const float*)d_in[6];
  float* out = (float*)d_out;

  prep_kernel<<<1, 1024>>>(cov, means, plr, tl, il);
  em_kernel<<<dim3(NAUG, BATCH), 64>>>(features, lengths);
  score_kernel<<<dim3(N1, BATCH), 256>>>(out);
}

// round 6
// speedup vs baseline: 1.6679x; 1.6188x over previous
#include <cuda_runtime.h>
#include <math.h>

#define BIG_NEG -1000000000.0f
#define D     64
#define C1    32
#define CAUG  33
#define N1    512
#define NAUG  513
#define KK    32
#define BATCH 4
#define GJW   17            // float4s per row (68 floats: 64 + 4 pad)

// Scratch (allocations forbidden -> device globals)
__device__ float g_Minv[D * D];
__device__ float g_logdet;
__device__ float g_trans_aug[CAUG * CAUG];
__device__ float g_init_aug[CAUG];
__device__ float g_len_aug[KK * CAUG];
__device__ float g_vc[C1 * D];
__device__ float g_qc[C1];
__device__ float g_em_aug[BATCH * NAUG * CAUG];

// ---------------------------------------------------------------------------
// Kernel A: inverse + logdet ONLY (tables moved to em grid).
// In-place Gauss-Jordan exchange step, float4 rows, STATIC ping-pong
// (unroll-by-2 with named buffers -> LDS/STS with immediate bases).
//   p = 1/a_kk ; b_kk = p ; b_kj = a_kj*p ; b_ik = -a_ik*p ;
//   b_ij = a_ij - a_ik*p*a_kj
// ---------------------------------------------------------------------------
__global__ __launch_bounds__(1024) void prep_inv_kernel(
    const float* __restrict__ cov, const float* __restrict__ means) {
  __shared__ float4 A4[D * GJW];
  __shared__ float4 B4[D * GJW];
  int tid = threadIdx.x;
  int i = tid >> 4;          // row 0..63
  int q = tid & 15;          // float4 column index 0..15 (cols 4q..4q+3)

  {
    const float4* c4 = (const float4*)cov;   // cov rows are 64 floats, 16B ok
    A4[i * GJW + q] = c4[i * 16 + q];
  }
  __syncthreads();

  float lacc = 0.0f;

#define GJ_STEP(S4, D4, kk)                                              \
  {                                                                      \
    const float* S = (const float*)(S4);                                 \
    float piv = S[(kk)*4 * GJW + (kk)];                                  \
    float p = __fdividef(1.0f, piv);                                     \
    float aik = S[i * 4 * GJW + (kk)];                                   \
    float4 pr = (S4)[(kk)*GJW + q];                                      \
    float4 mr = (S4)[i * GJW + q];                                       \
    if (tid == 0) lacc += __logf(piv);                                   \
    float f = -aik * p;                                                  \
    float4 v;                                                            \
    v.x = fmaf(f, pr.x, mr.x);                                           \
    v.y = fmaf(f, pr.y, mr.y);                                           \
    v.z = fmaf(f, pr.z, mr.z);                                           \
    v.w = fmaf(f, pr.w, mr.w);                                           \
    if (i == (kk)) {                                                     \
      v.x = pr.x * p; v.y = pr.y * p; v.z = pr.z * p; v.w = pr.w * p;    \
    }                                                                    \
    if (((kk) >> 2) == q) {                                              \
      float repl = (i == (kk)) ? p : f;                                  \
      int cc = (kk) & 3;                                                 \
      if (cc == 0) v.x = repl;                                           \
      else if (cc == 1) v.y = repl;                                      \
      else if (cc == 2) v.z = repl;                                      \
      else v.w = repl;                                                   \
    }                                                                    \
    (D4)[i * GJW + q] = v;                                               \
    __syncthreads();                                                     \
  }

#pragma unroll 1
  for (int k = 0; k < D; k += 2) {
    GJ_STEP(A4, B4, k);
    GJ_STEP(B4, A4, k + 1);
  }
#undef GJ_STEP
  // result in A4
  if (tid == 0) g_logdet = lacc;

  const float* Sf = (const float*)A4;
  // Minv -> global (for em)
  for (int e = tid; e < D * D; e += 1024)
    g_Minv[e] = Sf[(e >> 6) * 4 * GJW + (e & 63)];

  // v_c[c][d] = sum_e Minv[d][e] * means[c][e]
  for (int e = tid; e < C1 * D; e += 1024) {
    int c = e >> 6, dd = e & 63;
    float s = 0.0f;
#pragma unroll 8
    for (int ee = 0; ee < D; ee++)
      s += Sf[dd * 4 * GJW + ee] * means[c * D + ee];
    g_vc[e] = s;
  }
  __syncthreads();

  if (tid < C1) {
    float s = 0.0f;
#pragma unroll 8
    for (int ee = 0; ee < D; ee++) s += means[tid * D + ee] * g_vc[tid * D + ee];
    g_qc[tid] = s;
  }
}

// ---------------------------------------------------------------------------
// Kernel B: em_aug[b][n][c]; one block per (n, b), 64 threads.
// Extra plane n == NAUG (bb == 0) computes the softmax/len tables in
// parallel (they don't depend on the inverse; score consumes them later).
// ---------------------------------------------------------------------------
__global__ __launch_bounds__(64) void em_kernel(
    const float* __restrict__ features, const int* __restrict__ lengths,
    const float* __restrict__ plr, const float* __restrict__ tl,
    const float* __restrict__ il) {
  int n = blockIdx.x;   // 0..513 (513 = tables block)
  int bb = blockIdx.y;  // 0..3
  int tid = threadIdx.x;
  int lane = tid & 31, w = tid >> 5;

  if (n == NAUG) {  // ---- tables block ----
    if (bb != 0) return;
    // trans log_softmax over axis 0 (per column), diag masked
    for (int col = w; col < C1; col += 2) {
      float x = (lane == col) ? BIG_NEG : tl[lane * C1 + col];
      float m = x;
#pragma unroll
      for (int o = 16; o; o >>= 1) m = fmaxf(m, __shfl_xor_sync(0xffffffffu, m, o));
      float s = expf(x - m);
#pragma unroll
      for (int o = 16; o; o >>= 1) s += __shfl_xor_sync(0xffffffffu, s, o);
      g_trans_aug[lane * CAUG + col] = (x - m) - logf(s);
    }
    if (w == 0) {  // init softmax
      float x = il[lane];
      float m = x;
#pragma unroll
      for (int o = 16; o; o >>= 1) m = fmaxf(m, __shfl_xor_sync(0xffffffffu, m, o));
      float s = expf(x - m);
#pragma unroll
      for (int o = 16; o; o >>= 1) s += __shfl_xor_sync(0xffffffffu, s, o);
      g_init_aug[lane] = (x - m) - logf(s);
      if (lane == 0) g_init_aug[C1] = BIG_NEG;
    }
    if (tid < CAUG) g_trans_aug[C1 * CAUG + tid] = 0.0f;          // row C1
    if (tid < C1) g_trans_aug[tid * CAUG + C1] = BIG_NEG;         // col C1

    __shared__ float lg[KK], ep[C1], pl[C1];
    if (tid < KK) lg[tid] = lgammaf((float)(tid + 1));
    if (tid < C1) { pl[tid] = plr[tid]; ep[tid] = expf(plr[tid]); }
    __syncthreads();
    for (int e = tid; e < KK * CAUG; e += 64) {
      int k = e / CAUG, j = e - k * CAUG;
      g_len_aug[e] = (j < C1)
          ? fmaf((float)k, pl[j], -ep[j]) - lg[k]
          : ((k == 1) ? 0.0f : BIG_NEG);
    }
    return;
  }

  // ---- em rows ----
  float* row = &g_em_aug[(bb * NAUG + n) * CAUG];

  bool isLen = false;
#pragma unroll
  for (int q = 0; q < BATCH; q++) isLen |= (lengths[q] == n);
  float eos = isLen ? 0.0f : BIG_NEG;  // shared across batch (matches reference)

  int len = lengths[bb];
  if (n >= len) {  // covers n == N1 too (len <= 512)
    if (tid < C1) row[tid] = BIG_NEG;
    if (tid == C1) row[C1] = eos;
    return;
  }

  __shared__ float f[D];
  __shared__ float red[D];
  f[tid] = features[((size_t)(bb * N1 + n)) * D + tid];
  __syncthreads();

  float s = 0.0f;
  const float* Mrow = &g_Minv[tid * D];
#pragma unroll 8
  for (int e = 0; e < D; e++) s += Mrow[e] * f[e];
  red[tid] = s * f[tid];
  __syncthreads();

  if (tid == C1) row[C1] = eos;
  if (tid < 32) {
    float v = red[tid] + red[tid + 32];
#pragma unroll
    for (int o = 16; o; o >>= 1) v += __shfl_xor_sync(0xffffffffu, v, o);
    float dot = 0.0f;
    const float* vc = &g_vc[tid * D];
#pragma unroll 8
    for (int e = 0; e < D; e++) dot += vc[e] * f[e];
    // d*log(2*pi) = 117.6241322501981
    float em = -0.5f * (v + g_qc[tid] - 2.0f * dot + 117.6241322501981f + g_logdet);
    row[tid] = em;
  }
}

// ---------------------------------------------------------------------------
// Kernel C: the 285 MB store kernel. One block per (t, b).
// out[k,i,j] = T[i,j] + A[k,j]  (+ em_last[b,i] on the single k = 512 - t)
// Plain STG (the __stcs variant measured ~38us slower).
// ---------------------------------------------------------------------------
__global__ __launch_bounds__(256) void score_kernel(float* __restrict__ out) {
  int t = blockIdx.x;   // 0..511
  int bb = blockIdx.y;  // 0..3
  int tid = threadIdx.x;

  __shared__ float T[CAUG * CAUG];          // 1089
  __shared__ float Arr[KK * CAUG];          // 1056: len_aug + wins (+ init at t=0)
  __shared__ float E[CAUG];                 // em_last[b][:]
  __shared__ float Wrow[(KK - 1) * CAUG];   // em_aug rows t .. t+30 (0 past end)

  for (int e = tid; e < CAUG * CAUG; e += 256) T[e] = g_trans_aug[e];
  if (tid < CAUG) E[tid] = g_em_aug[(bb * NAUG + N1) * CAUG + tid];
  for (int e = tid; e < (KK - 1) * CAUG; e += 256) {
    int r = e / CAUG, j = e - r * CAUG;
    int n = t + r;
    Wrow[e] = (n <= N1) ? g_em_aug[(bb * NAUG + n) * CAUG + j] : 0.0f;
  }
  __syncthreads();

  // windowed running sums: wins[k] = sum of em rows t..t+k-1 (clipped)
  if (tid < CAUG) {
    int j = tid;
    float ia = (t == 0) ? g_init_aug[j] : 0.0f;
    float w = 0.0f;
    Arr[j] = g_len_aug[j] + ia;  // k = 0: empty window
#pragma unroll
    for (int k = 1; k < KK; k++) {
      w += Wrow[(k - 1) * CAUG + j];
      Arr[k * CAUG + j] = w + g_len_aug[k * CAUG + j] + ia;
    }
  }
  __syncthreads();

  float* obase = out + (size_t)(bb * N1 + t) * (KK * CAUG * CAUG);

  for (int pos = tid; pos < CAUG * CAUG; pos += 256) {
    float tv = T[pos];
    int j = pos % CAUG;
    float* op = obase + pos;
#pragma unroll
    for (int k = 0; k < KK; k++)
      op[k * CAUG * CAUG] = tv + Arr[k * CAUG + j];  // coalesced STG.32
  }

  // rare per-i correction: t + k == 512, k in [1,31]  (t in [481,511])
  int kspec = N1 - t;
  if (kspec >= 1 && kspec < KK) {
    for (int pos = tid; pos < CAUG * CAUG; pos += 256) {
      int i2 = pos / CAUG;
      int j = pos - i2 * CAUG;
      // same thread rewrote same address in the loop above -> ordered, OK
      obase[kspec * CAUG * CAUG + pos] = T[pos] + Arr[kspec * CAUG + j] + E[i2];
    }
  }
}

// ---------------------------------------------------------------------------
extern "C" void kernel_launch(void* const* d_in, const int* in_sizes, int n_in,
                              void* d_out, int out_size) {
  const float* features = (const float*)d_in[0];
  const int*   lengths  = (const int*)d_in[1];
  const float* means    = (const float*)d_in[2];
  const float* cov      = (const float*)d_in[3];
  const float* plr      = (const float*)d_in[4];
  const float* tl       = (const float*)d_in[5];
  const float* il       = (const float*)d_in[6];
  float* out = (float*)d_out;

  prep_inv_kernel<<<1, 1024>>>(cov, means);
  em_kernel<<<dim3(NAUG + 1, BATCH), 64>>>(features, lengths, plr, tl, il);
  score_kernel<<<dim3(N1, BATCH), 256>>>(out);
}